// round 14
// baseline (speedup 1.0000x reference)
#include <cuda_runtime.h>
#include <cuda_fp16.h>
#include <math.h>

#define DIMV 1024
#define NH 16
#define HD 64
#define BB 2
#define SS 2048
#define MTOT (BB*SS)
#define KDIM 1024

// Scratch buffers.
__device__ __half g_xh  [MTOT*KDIM];        // x fp16 [M][K]
__device__ __half g_wqt [3*DIMV*KDIM];      // W_qkv^T fp16 [N=3072][K]
__device__ __half g_wot [DIMV*KDIM];        // W_out^T fp16 [N=1024][K]
__device__ __half g_q   [BB*NH*SS*HD];      // [b,h,s,d]  (pre-scaled by 1/8*log2e)
__device__ __half g_k   [BB*NH*SS*HD];      // [b,h,s,d]
__device__ __half g_vt  [BB*NH*HD*SS];      // [b,h,d,s]
__device__ __half g_atth[MTOT*DIMV];        // attention out fp16 [b*s][dim]

#define QSCALE (0.125f * 1.44269504088896f)

// ---------------------------------------------------------------------------
// helpers
// ---------------------------------------------------------------------------
__device__ __forceinline__ float ex2f(float x) {
    float y; asm("ex2.approx.f32 %0, %1;" : "=f"(y) : "f"(x)); return y;
}
__device__ __forceinline__ unsigned pack2(float a, float b) {
    __half2 h = __floats2half2_rn(a, b); return *(unsigned*)&h;
}
// packed half2 = {lo=a, hi=b}
__device__ __forceinline__ unsigned cvt_h2(float a, float b) {
    unsigned r;
    asm("cvt.rn.f16x2.f32 %0, %1, %2;" : "=r"(r) : "f"(b), "f"(a));
    return r;
}
__device__ __forceinline__ unsigned ex2_h2(unsigned x) {
    unsigned r;
    asm("ex2.approx.f16x2 %0, %1;" : "=r"(r) : "r"(x));
    return r;
}
__device__ __forceinline__ void mma_f16(float* c, const unsigned* a, const unsigned* b) {
    asm volatile(
        "mma.sync.aligned.m16n8k16.row.col.f32.f16.f16.f32 "
        "{%0,%1,%2,%3}, {%4,%5,%6,%7}, {%8,%9}, {%0,%1,%2,%3};"
        : "+f"(c[0]), "+f"(c[1]), "+f"(c[2]), "+f"(c[3])
        : "r"(a[0]), "r"(a[1]), "r"(a[2]), "r"(a[3]), "r"(b[0]), "r"(b[1]));
}
// rows of 64 halves (128B), 16B-chunk XOR swizzle. Returns half-index.
__device__ __forceinline__ int fsw(int r, int k) {
    return r * 64 + (k & 7) + ((((k >> 3) ^ r) & 7)) * 8;
}
// rows of 32 halves (64B), 16B-chunk XOR swizzle: c' = c ^ ((r ^ (r>>2)) & 3).
// Rows 0..7 at fixed chunk -> bank bases {0,20,8,28,4,16,12,24}: conflict-free.
__device__ __forceinline__ int gsw32(int r, int k) {
    return r * 32 + (k & 7) + ((((k >> 3) ^ r ^ (r >> 2)) & 3)) * 8;
}
__device__ __forceinline__ unsigned smem_u32(const void* p) {
    unsigned a;
    asm("{ .reg .u64 t; cvta.to.shared.u64 t, %1; cvt.u32.u64 %0, t; }" : "=r"(a) : "l"(p));
    return a;
}
__device__ __forceinline__ void ldsm4(unsigned* r, unsigned addr) {
    asm volatile("ldmatrix.sync.aligned.m8n8.x4.shared.b16 {%0,%1,%2,%3}, [%4];"
                 : "=r"(r[0]), "=r"(r[1]), "=r"(r[2]), "=r"(r[3]) : "r"(addr));
}
// A-fragment (m16 x k16) on 128B rows
__device__ __forceinline__ void ldsmA(unsigned* r, unsigned tbase, int mbase, int kbase, int lane) {
    int row = mbase + (lane & 8) + (lane & 7);
    int col = kbase + (lane >> 4) * 8;
    ldsm4(r, tbase + 2 * fsw(row, col));
}
// B-fragment pair on [n][k] storage, 128B rows
__device__ __forceinline__ void ldsmB(unsigned* r, unsigned tbase, int nbase, int kbase, int lane) {
    int row = nbase + ((lane & 16) >> 1) + (lane & 7);
    int col = kbase + ((lane >> 3) & 1) * 8;
    ldsm4(r, tbase + 2 * fsw(row, col));
}
// Same fragments on 64B rows (BK=32 GEMM tiles)
__device__ __forceinline__ void ldsmA32(unsigned* r, unsigned tbase, int mbase, int kbase, int lane) {
    int row = mbase + (lane & 8) + (lane & 7);
    int col = kbase + (lane >> 4) * 8;
    ldsm4(r, tbase + 2 * gsw32(row, col));
}
__device__ __forceinline__ void ldsmB32(unsigned* r, unsigned tbase, int nbase, int kbase, int lane) {
    int row = nbase + ((lane & 16) >> 1) + (lane & 7);
    int col = kbase + ((lane >> 3) & 1) * 8;
    ldsm4(r, tbase + 2 * gsw32(row, col));
}
__device__ __forceinline__ void cp16(unsigned dst, const void* src) {
    asm volatile("cp.async.cg.shared.global [%0], [%1], 16;" :: "r"(dst), "l"(src) : "memory");
}
__device__ __forceinline__ void cp_commit() {
    asm volatile("cp.async.commit_group;" ::: "memory");
}
template<int N> __device__ __forceinline__ void cp_wait() {
    asm volatile("cp.async.wait_group %0;" :: "n"(N) : "memory");
}

// ---------------------------------------------------------------------------
// Staging kernels
// ---------------------------------------------------------------------------
__global__ __launch_bounds__(256) void convert_x(const float* __restrict__ x, __half* __restrict__ xh) {
    int idx = blockIdx.x * 256 + threadIdx.x;      // float4 index
    float4 v = ((const float4*)x)[idx];
    ((uint2*)xh)[idx] = make_uint2(pack2(v.x, v.y), pack2(v.z, v.w));
}
__global__ __launch_bounds__(256) void transpose_w(const float* __restrict__ W, __half* __restrict__ Wt, int N) {
    __shared__ float t[32][33];
    const int tid = threadIdx.x;
    const int k0 = blockIdx.x * 32, n0 = blockIdx.y * 32;
#pragma unroll
    for (int r = 0; r < 4; r++) {
        int k = (tid >> 5) + r * 8;
        int n = tid & 31;
        t[k][n] = W[(size_t)(k0 + k) * N + n0 + n];
    }
    __syncthreads();
#pragma unroll
    for (int r = 0; r < 2; r++) {
        int n  = (tid >> 4) + r * 16;
        int kh = tid & 15;
        *(__half2*)&Wt[(size_t)(n0 + n) * KDIM + k0 + 2 * kh] =
            __floats2half2_rn(t[2 * kh][n], t[2 * kh + 1][n]);
    }
}

// ---------------------------------------------------------------------------
// HMMA GEMM: C[M,N] = A[M,K] @ Bt[N,K]^T + bias.  fp16 operands in gmem.
// Tiles 128x128, BK=32, 3-stage cp.async ring (48KB), one sync/chunk,
// 256 thr / 3 CTAs per SM (24 warps), warp tile 32x64, ldmatrix fragments.
// ---------------------------------------------------------------------------
#define GSTAGE 16384                    // A 8KB + B 8KB per stage
#define GEMM_SMEM (3 * GSTAGE)          // 49152 B

template<int MODE>
__global__ __launch_bounds__(256, 3)
void gemm_hmma(const __half* __restrict__ A, const __half* __restrict__ Bt,
               const float* __restrict__ bias, float* __restrict__ C, int N)
{
    extern __shared__ char sm[];
    const unsigned sbase = smem_u32(sm);

    const int tid  = threadIdx.x;
    const int lane = tid & 31;
    const int w    = tid >> 5;
    const int g    = lane >> 2;
    const int tig  = lane & 3;
    const int moff = 32 * (w & 3);
    const int noff = 64 * (w >> 2);
    const int bm   = blockIdx.y * 128;
    const int bn   = blockIdx.x * 128;

    float acc[2][8][4];
#pragma unroll
    for (int mt = 0; mt < 2; mt++)
#pragma unroll
        for (int nt = 0; nt < 8; nt++)
#pragma unroll
            for (int i = 0; i < 4; i++) acc[mt][nt][i] = 0.f;

    // loader: 128 rows x 32 halves = 512 x 16B chunks per operand;
    // thread t covers row = t>>1, chunks 2*(t&1) and 2*(t&1)+1.
    const int lrow = tid >> 1;
    const int lc0  = (tid & 1) * 2;

    auto cp_chunk = [&](int c, int buf) {
        const unsigned ab = sbase + buf * GSTAGE;
        const unsigned bb = ab + 8192;
        const __half* ap = &A [(size_t)(bm + lrow) * KDIM + c * 32];
        const __half* bp = &Bt[(size_t)(bn + lrow) * KDIM + c * 32];
        cp16(ab + 2 * gsw32(lrow, (lc0 + 0) * 8), ap + (lc0 + 0) * 8);
        cp16(ab + 2 * gsw32(lrow, (lc0 + 1) * 8), ap + (lc0 + 1) * 8);
        cp16(bb + 2 * gsw32(lrow, (lc0 + 0) * 8), bp + (lc0 + 0) * 8);
        cp16(bb + 2 * gsw32(lrow, (lc0 + 1) * 8), bp + (lc0 + 1) * 8);
        cp_commit();
    };

    const int NCH = KDIM / 32;   // 32
    cp_chunk(0, 0);
    cp_chunk(1, 1);

    for (int c = 0; c < NCH; c++) {
        if (c < NCH - 1) cp_wait<1>(); else cp_wait<0>();
        __syncthreads();
        if (c + 2 < NCH) cp_chunk(c + 2, (c + 2) % 3);

        const int buf = c % 3;
        const unsigned aB = sbase + buf * GSTAGE;
        const unsigned bB = aB + 8192;
#pragma unroll
        for (int ks = 0; ks < 2; ks++) {
            unsigned af[2][4], bf[8][2];
#pragma unroll
            for (int mt = 0; mt < 2; mt++)
                ldsmA32(af[mt], aB, moff + 16 * mt, 16 * ks, lane);
#pragma unroll
            for (int ntp = 0; ntp < 4; ntp++) {
                unsigned t4[4];
                ldsmB32(t4, bB, noff + 16 * ntp, 16 * ks, lane);
                bf[2 * ntp][0]     = t4[0]; bf[2 * ntp][1]     = t4[1];
                bf[2 * ntp + 1][0] = t4[2]; bf[2 * ntp + 1][1] = t4[3];
            }
#pragma unroll
            for (int mt = 0; mt < 2; mt++)
#pragma unroll
                for (int nt = 0; nt < 8; nt++)
                    mma_f16(acc[mt][nt], af[mt], bf[nt]);
        }
    }

    // epilogue
#pragma unroll
    for (int mt = 0; mt < 2; mt++) {
#pragma unroll
        for (int nt = 0; nt < 8; nt++) {
            const int n = bn + noff + 8 * nt + 2 * tig;
            const float bz0 = bias[n], bz1 = bias[n + 1];
#pragma unroll
            for (int half_i = 0; half_i < 2; half_i++) {
                const int m = bm + moff + 16 * mt + g + half_i * 8;
                float v0 = acc[mt][nt][half_i * 2 + 0] + bz0;
                float v1 = acc[mt][nt][half_i * 2 + 1] + bz1;
                if (MODE == 0) {
                    const int which = n >> 10;
                    const int hw = n & 1023;
                    const int hh = hw >> 6;
                    const int dd = hw & 63;
                    const int bI = m >> 11;
                    const int sI = m & 2047;
                    if (which == 2) {
                        const size_t base = ((size_t)(bI * NH + hh) * HD + dd) * SS + sI;
                        g_vt[base]      = __float2half_rn(v0);
                        g_vt[base + SS] = __float2half_rn(v1);
                    } else if (which == 0) {
                        *(__half2*)&g_q[((size_t)(bI * NH + hh) * SS + sI) * HD + dd] =
                            __floats2half2_rn(v0 * QSCALE, v1 * QSCALE);
                    } else {
                        *(__half2*)&g_k[((size_t)(bI * NH + hh) * SS + sI) * HD + dd] =
                            __floats2half2_rn(v0, v1);
                    }
                } else {
                    *(float2*)&C[(size_t)m * N + n] = make_float2(v0, v1);
                }
            }
        }
    }
}

// ---------------------------------------------------------------------------
// Flash attention, fp16 MMA + ldmatrix + 3-stage cp.async K/V ring.
// 128 q-rows/CTA, key tiles of 64, 8 warps, target 3 CTAs/SM.
// dyn smem: Qs 16KB + 3 x (K 8KB + V 8KB) = 64KB.
// ---------------------------------------------------------------------------
#define FQ 0
#define FK(s) (16384 + (s) * 16384)
#define FV(s) (16384 + (s) * 16384 + 8192)
#define FLASH_SMEM 65536

__global__ __launch_bounds__(256, 3)
void flash_f16(const __half* __restrict__ Qg, const __half* __restrict__ Kg,
               const __half* __restrict__ Vtg, __half* __restrict__ Og)
{
    extern __shared__ char sm[];
    const unsigned sbase = smem_u32(sm);

    const int tid  = threadIdx.x;
    const int lane = tid & 31;
    const int w    = tid >> 5;
    const int g    = lane >> 2;
    const int tig  = lane & 3;

    const int qt = blockIdx.x;
    const int h  = blockIdx.y;
    const int b  = blockIdx.z;

    const __half* Qp  = Qg  + ((size_t)(b * NH + h) * SS + qt * 128) * HD;
    const __half* Kp  = Kg  + (size_t)(b * NH + h) * SS * HD;
    const __half* Vtp = Vtg + (size_t)(b * NH + h) * HD * SS;

    const int krow = tid >> 2;              // 0..63  (K/V tile row)
    const int kk8  = (tid & 3) * 16;        // two 16B chunks per thread per row
    auto cp_tile = [&](int kt, int s) {
        const unsigned kb = sbase + FK(s) + 2 * fsw(krow, kk8);
        const unsigned vb = sbase + FV(s) + 2 * fsw(krow, kk8);
        const __half* kp = &Kp [(size_t)(kt * 64 + krow) * HD + kk8];
        const __half* vp = &Vtp[(size_t)krow * SS + kt * 64 + kk8];
        cp16(kb, kp);                       cp16(vb, vp);
        cp16(kb + 2 * (fsw(krow, kk8 + 8) - fsw(krow, kk8)), kp + 8);
        cp16(vb + 2 * (fsw(krow, kk8 + 8) - fsw(krow, kk8)), vp + 8);
        cp_commit();
    };

    // ---- load Q tile (plain LDG/STS, once) ----
#pragma unroll
    for (int r = 0; r < 4; r++) {
        int idx = tid + r * 256;
        int row = idx >> 3;
        int k8  = (idx & 7) * 8;
        uint4 v = *(const uint4*)&Qp[row * HD + k8];
        *(uint4*)(sm + FQ + 2 * fsw(row, k8)) = v;
    }

    cp_tile(0, 0);
    cp_tile(1, 1);
    __syncthreads();   // Q visible

    unsigned qf[4][4];
#pragma unroll
    for (int dc = 0; dc < 4; dc++)
        ldsmA(qf[dc], sbase + FQ, 16 * w, 16 * dc, lane);

    float m0 = -1e30f, m1 = -1e30f, l0 = 0.f, l1 = 0.f;
    float Oa[8][4];
#pragma unroll
    for (int dt = 0; dt < 8; dt++)
#pragma unroll
        for (int i = 0; i < 4; i++) Oa[dt][i] = 0.f;

    const unsigned ONES2[2] = { 0x3C003C00u, 0x3C003C00u };

    const int NT = SS / 64;   // 32
    for (int kt = 0; kt < NT; kt++) {
        if (kt < NT - 1) cp_wait<1>(); else cp_wait<0>();
        __syncthreads();
        if (kt + 2 < NT) cp_tile(kt + 2, (kt + 2) % 3);

        const int buf = kt % 3;
        const unsigned kB = sbase + FK(buf);
        const unsigned vB = sbase + FV(buf);

        // ---- S = Q @ K^T (already log2-scaled via Q) ----
        float S[8][4];
#pragma unroll
        for (int nt = 0; nt < 8; nt++)
#pragma unroll
            for (int i = 0; i < 4; i++) S[nt][i] = 0.f;
#pragma unroll
        for (int dc = 0; dc < 4; dc++) {
#pragma unroll
            for (int ntp = 0; ntp < 4; ntp++) {
                unsigned t4[4];
                ldsmB(t4, kB, 16 * ntp, 16 * dc, lane);
                mma_f16(S[2 * ntp],     qf[dc], t4);
                mma_f16(S[2 * ntp + 1], qf[dc], t4 + 2);
            }
        }

        // ---- online max ----
        float mx0 = S[0][0], mx1 = S[0][2];
#pragma unroll
        for (int nt = 0; nt < 8; nt++) {
            mx0 = fmaxf(mx0, fmaxf(S[nt][0], S[nt][1]));
            mx1 = fmaxf(mx1, fmaxf(S[nt][2], S[nt][3]));
        }
        mx0 = fmaxf(mx0, __shfl_xor_sync(0xffffffffu, mx0, 1));
        mx0 = fmaxf(mx0, __shfl_xor_sync(0xffffffffu, mx0, 2));
        mx1 = fmaxf(mx1, __shfl_xor_sync(0xffffffffu, mx1, 1));
        mx1 = fmaxf(mx1, __shfl_xor_sync(0xffffffffu, mx1, 2));

        const float mn0 = fmaxf(m0, mx0);
        const float mn1 = fmaxf(m1, mx1);
        const float al0 = ex2f(m0 - mn0);
        const float al1 = ex2f(m1 - mn1);
        m0 = mn0; m1 = mn1;

        // ---- P = 2^(S-m) in f16x2, born as packed A-fragments ----
        unsigned P[8][2];
#pragma unroll
        for (int nt = 0; nt < 8; nt++) {
            P[nt][0] = ex2_h2(cvt_h2(S[nt][0] - mn0, S[nt][1] - mn0));  // row g
            P[nt][1] = ex2_h2(cvt_h2(S[nt][2] - mn1, S[nt][3] - mn1));  // row g+8
        }

        // ---- rescale O ----
#pragma unroll
        for (int dt = 0; dt < 8; dt++) {
            Oa[dt][0] *= al0; Oa[dt][1] *= al0;
            Oa[dt][2] *= al1; Oa[dt][3] *= al1;
        }

        // ---- l partial via ones-MMA + O += P @ V ----
        float lacc[4] = {0.f, 0.f, 0.f, 0.f};
#pragma unroll
        for (int kc = 0; kc < 4; kc++) {
            unsigned pf[4];
            pf[0] = P[2 * kc][0];
            pf[1] = P[2 * kc][1];
            pf[2] = P[2 * kc + 1][0];
            pf[3] = P[2 * kc + 1][1];
            mma_f16(lacc, pf, ONES2);          // row sums -> lacc[0] (g), lacc[2] (g+8)
#pragma unroll
            for (int dtp = 0; dtp < 4; dtp++) {
                unsigned t4[4];
                ldsmB(t4, vB, 16 * dtp, 16 * kc, lane);
                mma_f16(Oa[2 * dtp],     pf, t4);
                mma_f16(Oa[2 * dtp + 1], pf, t4 + 2);
            }
        }
        l0 = l0 * al0 + lacc[0];
        l1 = l1 * al1 + lacc[2];
    }

    const float li0 = 1.f / l0;
    const float li1 = 1.f / l1;
    const int s0 = qt * 128 + 16 * w + g;
    const int s1 = s0 + 8;
#pragma unroll
    for (int dt = 0; dt < 8; dt++) {
        const int col = h * HD + 8 * dt + 2 * tig;
        *(__half2*)&Og[((size_t)(b * SS + s0)) * DIMV + col] =
            __floats2half2_rn(Oa[dt][0] * li0, Oa[dt][1] * li0);
        *(__half2*)&Og[((size_t)(b * SS + s1)) * DIMV + col] =
            __floats2half2_rn(Oa[dt][2] * li1, Oa[dt][3] * li1);
    }
}

// ---------------------------------------------------------------------------
extern "C" void kernel_launch(void* const* d_in, const int* in_sizes, int n_in,
                              void* d_out, int out_size)
{
    (void)in_sizes; (void)n_in; (void)out_size;
    const float* x     = (const float*)d_in[0];
    const float* W_qkv = (const float*)d_in[1];
    const float* b_qkv = (const float*)d_in[2];
    const float* W_out = (const float*)d_in[3];
    const float* b_out = (const float*)d_in[4];
    float* out = (float*)d_out;

    __half *xh, *wqt, *wot, *qb, *kb, *vtb, *ath;
    cudaGetSymbolAddress((void**)&xh,  g_xh);
    cudaGetSymbolAddress((void**)&wqt, g_wqt);
    cudaGetSymbolAddress((void**)&wot, g_wot);
    cudaGetSymbolAddress((void**)&qb,  g_q);
    cudaGetSymbolAddress((void**)&kb,  g_k);
    cudaGetSymbolAddress((void**)&vtb, g_vt);
    cudaGetSymbolAddress((void**)&ath, g_atth);

    static bool attr_set = false;
    if (!attr_set) {
        cudaFuncSetAttribute(gemm_hmma<0>, cudaFuncAttributeMaxDynamicSharedMemorySize, GEMM_SMEM);
        cudaFuncSetAttribute(gemm_hmma<1>, cudaFuncAttributeMaxDynamicSharedMemorySize, GEMM_SMEM);
        cudaFuncSetAttribute(flash_f16,    cudaFuncAttributeMaxDynamicSharedMemorySize, FLASH_SMEM);
        attr_set = true;
    }

    // 0. stage fp16 operands
    convert_x<<<MTOT * KDIM / 1024, 256>>>(x, xh);
    { dim3 g(KDIM / 32, 3 * DIMV / 32); transpose_w<<<g, 256>>>(W_qkv, wqt, 3 * DIMV); }
    { dim3 g(KDIM / 32, DIMV / 32);     transpose_w<<<g, 256>>>(W_out, wot, DIMV); }

    // 1. QKV GEMM -> fp16 Q(prescaled)/K head-layout + V^T
    { dim3 g(3 * DIMV / 128, MTOT / 128); gemm_hmma<0><<<g, 256, GEMM_SMEM>>>(xh, wqt, b_qkv, nullptr, 3 * DIMV); }
    // 2. Flash attention -> fp16 [b,s,dim]
    { dim3 g(SS / 128, NH, BB); flash_f16<<<g, 256, FLASH_SMEM>>>(qb, kb, vtb, ath); }
    // 3. Output projection -> fp32 out
    { dim3 g(DIMV / 128, MTOT / 128); gemm_hmma<1><<<g, 256, GEMM_SMEM>>>(ath, wot, b_out, out, DIMV); }
}

// round 15
// speedup vs baseline: 1.5155x; 1.5155x over previous
#include <cuda_runtime.h>
#include <cuda_fp16.h>
#include <math.h>

#define DIMV 1024
#define NH 16
#define HD 64
#define BB 2
#define SS 2048
#define MTOT (BB*SS)
#define KDIM 1024

// Scratch buffers.
__device__ __half g_wqt [3*DIMV*KDIM];      // W_qkv^T fp16 [N=3072][K]
__device__ __half g_wot [DIMV*KDIM];        // W_out^T fp16 [N=1024][K]
__device__ __half g_q   [BB*NH*SS*HD];      // [b,h,s,d]  (pre-scaled by 1/8*log2e)
__device__ __half g_k   [BB*NH*SS*HD];      // [b,h,s,d]
__device__ __half g_vt  [BB*NH*HD*SS];      // [b,h,d,s]
__device__ __half g_atth[MTOT*DIMV];        // attention out fp16 [b*s][dim]

#define QSCALE (0.125f * 1.44269504088896f)

// ---------------------------------------------------------------------------
// helpers
// ---------------------------------------------------------------------------
__device__ __forceinline__ float ex2f(float x) {
    float y; asm("ex2.approx.f32 %0, %1;" : "=f"(y) : "f"(x)); return y;
}
__device__ __forceinline__ unsigned pack2(float a, float b) {
    __half2 h = __floats2half2_rn(a, b); return *(unsigned*)&h;
}
// packed half2 = {lo=a, hi=b}
__device__ __forceinline__ unsigned cvt_h2(float a, float b) {
    unsigned r;
    asm("cvt.rn.f16x2.f32 %0, %1, %2;" : "=r"(r) : "f"(b), "f"(a));
    return r;
}
__device__ __forceinline__ unsigned ex2_h2(unsigned x) {
    unsigned r;
    asm("ex2.approx.f16x2 %0, %1;" : "=r"(r) : "r"(x));
    return r;
}
__device__ __forceinline__ void mma_f16(float* c, const unsigned* a, const unsigned* b) {
    asm volatile(
        "mma.sync.aligned.m16n8k16.row.col.f32.f16.f16.f32 "
        "{%0,%1,%2,%3}, {%4,%5,%6,%7}, {%8,%9}, {%0,%1,%2,%3};"
        : "+f"(c[0]), "+f"(c[1]), "+f"(c[2]), "+f"(c[3])
        : "r"(a[0]), "r"(a[1]), "r"(a[2]), "r"(a[3]), "r"(b[0]), "r"(b[1]));
}
// rows of 64 halves (128B), 16B-chunk XOR swizzle. Returns half-index.
__device__ __forceinline__ int fsw(int r, int k) {
    return r * 64 + (k & 7) + ((((k >> 3) ^ r) & 7)) * 8;
}
__device__ __forceinline__ unsigned smem_u32(const void* p) {
    unsigned a;
    asm("{ .reg .u64 t; cvta.to.shared.u64 t, %1; cvt.u32.u64 %0, t; }" : "=r"(a) : "l"(p));
    return a;
}
__device__ __forceinline__ void ldsm4(unsigned* r, unsigned addr) {
    asm volatile("ldmatrix.sync.aligned.m8n8.x4.shared.b16 {%0,%1,%2,%3}, [%4];"
                 : "=r"(r[0]), "=r"(r[1]), "=r"(r[2]), "=r"(r[3]) : "r"(addr));
}
// A-fragment (m16 x k16): regs = {mlo/klo, mhi/klo, mlo/khi, mhi/khi}
__device__ __forceinline__ void ldsmA(unsigned* r, unsigned tbase, int mbase, int kbase, int lane) {
    int row = mbase + (lane & 8) + (lane & 7);
    int col = kbase + (lane >> 4) * 8;
    ldsm4(r, tbase + 2 * fsw(row, col));
}
// B-fragment pair on [n][k] storage: regs = {b0,b1 of nt_lo, b0,b1 of nt_hi}
__device__ __forceinline__ void ldsmB(unsigned* r, unsigned tbase, int nbase, int kbase, int lane) {
    int row = nbase + ((lane & 16) >> 1) + (lane & 7);
    int col = kbase + ((lane >> 3) & 1) * 8;
    ldsm4(r, tbase + 2 * fsw(row, col));
}
__device__ __forceinline__ void cp16(unsigned dst, const void* src) {
    asm volatile("cp.async.cg.shared.global [%0], [%1], 16;" :: "r"(dst), "l"(src) : "memory");
}
__device__ __forceinline__ void cp_commit() {
    asm volatile("cp.async.commit_group;" ::: "memory");
}
template<int N> __device__ __forceinline__ void cp_wait() {
    asm volatile("cp.async.wait_group %0;" :: "n"(N) : "memory");
}

// ---------------------------------------------------------------------------
// Staging: weight transpose fp32 [K][N] -> fp16 [N][K]
// ---------------------------------------------------------------------------
__global__ __launch_bounds__(256) void transpose_w(const float* __restrict__ W, __half* __restrict__ Wt, int N) {
    __shared__ float t[32][33];
    const int tid = threadIdx.x;
    const int k0 = blockIdx.x * 32, n0 = blockIdx.y * 32;
#pragma unroll
    for (int r = 0; r < 4; r++) {
        int k = (tid >> 5) + r * 8;
        int n = tid & 31;
        t[k][n] = W[(size_t)(k0 + k) * N + n0 + n];
    }
    __syncthreads();
#pragma unroll
    for (int r = 0; r < 2; r++) {
        int n  = (tid >> 4) + r * 16;
        int kh = tid & 15;
        *(__half2*)&Wt[(size_t)(n0 + n) * KDIM + k0 + 2 * kh] =
            __floats2half2_rn(t[2 * kh][n], t[2 * kh + 1][n]);
    }
}

#define GSTAGE 32768
#define GEMM_SMEM (3 * GSTAGE)   // 98304 B

// ---------------------------------------------------------------------------
// QKV GEMM: A fp32 (x) converted inline in the A-loader; B fp16 via cp.async.
// Tiles 128x128, BK=64, 3-stage ring, one sync/chunk, 8 warps, warp tile 32x64.
// Epilogue scatters fp16 Q(prescaled)/K [b,h,s,d] and V^T [b,h,d,s].
// ---------------------------------------------------------------------------
__global__ __launch_bounds__(256, 2)
void gemm_qkv(const float* __restrict__ A, const __half* __restrict__ Bt,
              const float* __restrict__ bias)
{
    extern __shared__ char sm[];
    const unsigned sbase = smem_u32(sm);

    const int tid  = threadIdx.x;
    const int lane = tid & 31;
    const int w    = tid >> 5;
    const int g    = lane >> 2;
    const int tig  = lane & 3;
    const int moff = 32 * (w & 3);
    const int noff = 64 * (w >> 2);
    const int bm   = blockIdx.y * 128;
    const int bn   = blockIdx.x * 128;

    float acc[2][8][4];
#pragma unroll
    for (int mt = 0; mt < 2; mt++)
#pragma unroll
        for (int nt = 0; nt < 8; nt++)
#pragma unroll
            for (int i = 0; i < 4; i++) acc[mt][nt][i] = 0.f;

    const int row = tid >> 3;            // 0..31 (+32*r)
    const int k8  = (tid & 7) * 8;
    const int swo = 2 * fsw(row, k8);    // byte offset within a tile

    // A: LDG fp32 -> cvt -> STS (fused convert).  B: cp.async fp16.
    auto ld_chunk = [&](int c, int buf) {
        const unsigned ab = sbase + buf * GSTAGE + swo;
        const unsigned bb = ab + 16384;
        const float*  ap = &A [(size_t)(bm + row) * KDIM + c * 64 + k8];
        const __half* bp = &Bt[(size_t)(bn + row) * KDIM + c * 64 + k8];
#pragma unroll
        for (int r = 0; r < 4; r++) {
            float4 v0 = *(const float4*)(ap + (size_t)(32 * r) * KDIM);
            float4 v1 = *(const float4*)(ap + (size_t)(32 * r) * KDIM + 4);
            *(uint4*)(sm + (ab - sbase) + r * 32 * 128) =
                make_uint4(pack2(v0.x, v0.y), pack2(v0.z, v0.w),
                           pack2(v1.x, v1.y), pack2(v1.z, v1.w));
            cp16(bb + r * 32 * 128, bp + (size_t)(32 * r) * KDIM);
        }
        cp_commit();
    };

    const int NCH = KDIM / 64;   // 16
    ld_chunk(0, 0);
    ld_chunk(1, 1);

    for (int c = 0; c < NCH; c++) {
        if (c < NCH - 1) cp_wait<1>(); else cp_wait<0>();
        __syncthreads();
        if (c + 2 < NCH) ld_chunk(c + 2, (c + 2) % 3);

        const int buf = c % 3;
        const unsigned aB = sbase + buf * GSTAGE;
        const unsigned bB = aB + 16384;
#pragma unroll
        for (int ks = 0; ks < 4; ks++) {
            unsigned af[2][4], bf[8][2];
#pragma unroll
            for (int mt = 0; mt < 2; mt++)
                ldsmA(af[mt], aB, moff + 16 * mt, 16 * ks, lane);
#pragma unroll
            for (int ntp = 0; ntp < 4; ntp++) {
                unsigned t4[4];
                ldsmB(t4, bB, noff + 16 * ntp, 16 * ks, lane);
                bf[2 * ntp][0]     = t4[0]; bf[2 * ntp][1]     = t4[1];
                bf[2 * ntp + 1][0] = t4[2]; bf[2 * ntp + 1][1] = t4[3];
            }
#pragma unroll
            for (int mt = 0; mt < 2; mt++)
#pragma unroll
                for (int nt = 0; nt < 8; nt++)
                    mma_f16(acc[mt][nt], af[mt], bf[nt]);
        }
    }

    // epilogue: scatter to head layouts
#pragma unroll
    for (int mt = 0; mt < 2; mt++) {
#pragma unroll
        for (int nt = 0; nt < 8; nt++) {
            const int n = bn + noff + 8 * nt + 2 * tig;
            const float bz0 = bias[n], bz1 = bias[n + 1];
#pragma unroll
            for (int half_i = 0; half_i < 2; half_i++) {
                const int m = bm + moff + 16 * mt + g + half_i * 8;
                float v0 = acc[mt][nt][half_i * 2 + 0] + bz0;
                float v1 = acc[mt][nt][half_i * 2 + 1] + bz1;
                const int which = n >> 10;
                const int hw = n & 1023;
                const int hh = hw >> 6;
                const int dd = hw & 63;
                const int bI = m >> 11;
                const int sI = m & 2047;
                if (which == 2) {
                    const size_t base = ((size_t)(bI * NH + hh) * HD + dd) * SS + sI;
                    g_vt[base]      = __float2half_rn(v0);
                    g_vt[base + SS] = __float2half_rn(v1);
                } else if (which == 0) {
                    *(__half2*)&g_q[((size_t)(bI * NH + hh) * SS + sI) * HD + dd] =
                        __floats2half2_rn(v0 * QSCALE, v1 * QSCALE);
                } else {
                    *(__half2*)&g_k[((size_t)(bI * NH + hh) * SS + sI) * HD + dd] =
                        __floats2half2_rn(v0, v1);
                }
            }
        }
    }
}

// ---------------------------------------------------------------------------
// Output projection GEMM: A fp16 (g_atth), B fp16 (g_wot), both cp.async.
// Identical pipeline; fp32 row-major output + bias.
// ---------------------------------------------------------------------------
__global__ __launch_bounds__(256)
void gemm_out(const __half* __restrict__ A, const __half* __restrict__ Bt,
              const float* __restrict__ bias, float* __restrict__ C, int N)
{
    extern __shared__ char sm[];
    const unsigned sbase = smem_u32(sm);

    const int tid  = threadIdx.x;
    const int lane = tid & 31;
    const int w    = tid >> 5;
    const int g    = lane >> 2;
    const int tig  = lane & 3;
    const int moff = 32 * (w & 3);
    const int noff = 64 * (w >> 2);
    const int bm   = blockIdx.y * 128;
    const int bn   = blockIdx.x * 128;

    float acc[2][8][4];
#pragma unroll
    for (int mt = 0; mt < 2; mt++)
#pragma unroll
        for (int nt = 0; nt < 8; nt++)
#pragma unroll
            for (int i = 0; i < 4; i++) acc[mt][nt][i] = 0.f;

    const int row = tid >> 3;
    const int k8  = (tid & 7) * 8;
    const int swo = 2 * fsw(row, k8);

    auto cp_chunk = [&](int c, int buf) {
        const unsigned ab = sbase + buf * GSTAGE + swo;
        const unsigned bb = ab + 16384;
        const __half* ap = &A [(size_t)(bm + row) * KDIM + c * 64 + k8];
        const __half* bp = &Bt[(size_t)(bn + row) * KDIM + c * 64 + k8];
#pragma unroll
        for (int r = 0; r < 4; r++) {
            cp16(ab + r * 32 * 128, ap + (size_t)(32 * r) * KDIM);
            cp16(bb + r * 32 * 128, bp + (size_t)(32 * r) * KDIM);
        }
        cp_commit();
    };

    const int NCH = KDIM / 64;   // 16
    cp_chunk(0, 0);
    cp_chunk(1, 1);

    for (int c = 0; c < NCH; c++) {
        if (c < NCH - 1) cp_wait<1>(); else cp_wait<0>();
        __syncthreads();
        if (c + 2 < NCH) cp_chunk(c + 2, (c + 2) % 3);

        const int buf = c % 3;
        const unsigned aB = sbase + buf * GSTAGE;
        const unsigned bB = aB + 16384;
#pragma unroll
        for (int ks = 0; ks < 4; ks++) {
            unsigned af[2][4], bf[8][2];
#pragma unroll
            for (int mt = 0; mt < 2; mt++)
                ldsmA(af[mt], aB, moff + 16 * mt, 16 * ks, lane);
#pragma unroll
            for (int ntp = 0; ntp < 4; ntp++) {
                unsigned t4[4];
                ldsmB(t4, bB, noff + 16 * ntp, 16 * ks, lane);
                bf[2 * ntp][0]     = t4[0]; bf[2 * ntp][1]     = t4[1];
                bf[2 * ntp + 1][0] = t4[2]; bf[2 * ntp + 1][1] = t4[3];
            }
#pragma unroll
            for (int mt = 0; mt < 2; mt++)
#pragma unroll
                for (int nt = 0; nt < 8; nt++)
                    mma_f16(acc[mt][nt], af[mt], bf[nt]);
        }
    }

#pragma unroll
    for (int mt = 0; mt < 2; mt++) {
#pragma unroll
        for (int nt = 0; nt < 8; nt++) {
            const int n = bn + noff + 8 * nt + 2 * tig;
            const float bz0 = bias[n], bz1 = bias[n + 1];
#pragma unroll
            for (int half_i = 0; half_i < 2; half_i++) {
                const int m = bm + moff + 16 * mt + g + half_i * 8;
                float v0 = acc[mt][nt][half_i * 2 + 0] + bz0;
                float v1 = acc[mt][nt][half_i * 2 + 1] + bz1;
                *(float2*)&C[(size_t)m * N + n] = make_float2(v0, v1);
            }
        }
    }
}

// ---------------------------------------------------------------------------
// Flash attention, fp16 MMA + ldmatrix + 3-stage cp.async K/V ring.
// (identical to the 241.6us R13 kernel)
// ---------------------------------------------------------------------------
#define FQ 0
#define FK(s) (16384 + (s) * 16384)
#define FV(s) (16384 + (s) * 16384 + 8192)
#define FLASH_SMEM 65536

__global__ __launch_bounds__(256)
void flash_f16(const __half* __restrict__ Qg, const __half* __restrict__ Kg,
               const __half* __restrict__ Vtg, __half* __restrict__ Og)
{
    extern __shared__ char sm[];
    const unsigned sbase = smem_u32(sm);

    const int tid  = threadIdx.x;
    const int lane = tid & 31;
    const int w    = tid >> 5;
    const int g    = lane >> 2;
    const int tig  = lane & 3;

    const int qt = blockIdx.x;
    const int h  = blockIdx.y;
    const int b  = blockIdx.z;

    const __half* Qp  = Qg  + ((size_t)(b * NH + h) * SS + qt * 128) * HD;
    const __half* Kp  = Kg  + (size_t)(b * NH + h) * SS * HD;
    const __half* Vtp = Vtg + (size_t)(b * NH + h) * HD * SS;

    const int krow = tid >> 2;              // 0..63  (K/V tile row)
    const int kk8  = (tid & 3) * 16;        // two 16B chunks per thread per row
    auto cp_tile = [&](int kt, int s) {
        const unsigned kb = sbase + FK(s) + 2 * fsw(krow, kk8);
        const unsigned vb = sbase + FV(s) + 2 * fsw(krow, kk8);
        const __half* kp = &Kp [(size_t)(kt * 64 + krow) * HD + kk8];
        const __half* vp = &Vtp[(size_t)krow * SS + kt * 64 + kk8];
        cp16(kb, kp);                       cp16(vb, vp);
        cp16(kb + 2 * (fsw(krow, kk8 + 8) - fsw(krow, kk8)), kp + 8);
        cp16(vb + 2 * (fsw(krow, kk8 + 8) - fsw(krow, kk8)), vp + 8);
        cp_commit();
    };

    // ---- load Q tile (plain LDG/STS, once) ----
#pragma unroll
    for (int r = 0; r < 4; r++) {
        int idx = tid + r * 256;
        int row = idx >> 3;
        int k8  = (idx & 7) * 8;
        uint4 v = *(const uint4*)&Qp[row * HD + k8];
        *(uint4*)(sm + FQ + 2 * fsw(row, k8)) = v;
    }

    cp_tile(0, 0);
    cp_tile(1, 1);
    __syncthreads();   // Q visible

    unsigned qf[4][4];
#pragma unroll
    for (int dc = 0; dc < 4; dc++)
        ldsmA(qf[dc], sbase + FQ, 16 * w, 16 * dc, lane);

    float m0 = -1e30f, m1 = -1e30f, l0 = 0.f, l1 = 0.f;
    float Oa[8][4];
#pragma unroll
    for (int dt = 0; dt < 8; dt++)
#pragma unroll
        for (int i = 0; i < 4; i++) Oa[dt][i] = 0.f;

    const unsigned ONES2[2] = { 0x3C003C00u, 0x3C003C00u };

    const int NT = SS / 64;   // 32
    for (int kt = 0; kt < NT; kt++) {
        if (kt < NT - 1) cp_wait<1>(); else cp_wait<0>();
        __syncthreads();
        if (kt + 2 < NT) cp_tile(kt + 2, (kt + 2) % 3);

        const int buf = kt % 3;
        const unsigned kB = sbase + FK(buf);
        const unsigned vB = sbase + FV(buf);

        // ---- S = Q @ K^T (already log2-scaled via Q) ----
        float S[8][4];
#pragma unroll
        for (int nt = 0; nt < 8; nt++)
#pragma unroll
            for (int i = 0; i < 4; i++) S[nt][i] = 0.f;
#pragma unroll
        for (int dc = 0; dc < 4; dc++) {
#pragma unroll
            for (int ntp = 0; ntp < 4; ntp++) {
                unsigned t4[4];
                ldsmB(t4, kB, 16 * ntp, 16 * dc, lane);
                mma_f16(S[2 * ntp],     qf[dc], t4);
                mma_f16(S[2 * ntp + 1], qf[dc], t4 + 2);
            }
        }

        // ---- online max ----
        float mx0 = S[0][0], mx1 = S[0][2];
#pragma unroll
        for (int nt = 0; nt < 8; nt++) {
            mx0 = fmaxf(mx0, fmaxf(S[nt][0], S[nt][1]));
            mx1 = fmaxf(mx1, fmaxf(S[nt][2], S[nt][3]));
        }
        mx0 = fmaxf(mx0, __shfl_xor_sync(0xffffffffu, mx0, 1));
        mx0 = fmaxf(mx0, __shfl_xor_sync(0xffffffffu, mx0, 2));
        mx1 = fmaxf(mx1, __shfl_xor_sync(0xffffffffu, mx1, 1));
        mx1 = fmaxf(mx1, __shfl_xor_sync(0xffffffffu, mx1, 2));

        const float mn0 = fmaxf(m0, mx0);
        const float mn1 = fmaxf(m1, mx1);
        const float al0 = ex2f(m0 - mn0);
        const float al1 = ex2f(m1 - mn1);
        m0 = mn0; m1 = mn1;

        // ---- P = 2^(S-m) in f16x2, born as packed A-fragments ----
        unsigned P[8][2];
#pragma unroll
        for (int nt = 0; nt < 8; nt++) {
            P[nt][0] = ex2_h2(cvt_h2(S[nt][0] - mn0, S[nt][1] - mn0));  // row g
            P[nt][1] = ex2_h2(cvt_h2(S[nt][2] - mn1, S[nt][3] - mn1));  // row g+8
        }

        // ---- rescale O ----
#pragma unroll
        for (int dt = 0; dt < 8; dt++) {
            Oa[dt][0] *= al0; Oa[dt][1] *= al0;
            Oa[dt][2] *= al1; Oa[dt][3] *= al1;
        }

        // ---- l partial via ones-MMA + O += P @ V ----
        float lacc[4] = {0.f, 0.f, 0.f, 0.f};
#pragma unroll
        for (int kc = 0; kc < 4; kc++) {
            unsigned pf[4];
            pf[0] = P[2 * kc][0];
            pf[1] = P[2 * kc][1];
            pf[2] = P[2 * kc + 1][0];
            pf[3] = P[2 * kc + 1][1];
            mma_f16(lacc, pf, ONES2);          // row sums -> lacc[0] (g), lacc[2] (g+8)
#pragma unroll
            for (int dtp = 0; dtp < 4; dtp++) {
                unsigned t4[4];
                ldsmB(t4, vB, 16 * dtp, 16 * kc, lane);
                mma_f16(Oa[2 * dtp],     pf, t4);
                mma_f16(Oa[2 * dtp + 1], pf, t4 + 2);
            }
        }
        l0 = l0 * al0 + lacc[0];
        l1 = l1 * al1 + lacc[2];
    }

    const float li0 = 1.f / l0;
    const float li1 = 1.f / l1;
    const int s0 = qt * 128 + 16 * w + g;
    const int s1 = s0 + 8;
#pragma unroll
    for (int dt = 0; dt < 8; dt++) {
        const int col = h * HD + 8 * dt + 2 * tig;
        *(__half2*)&Og[((size_t)(b * SS + s0)) * DIMV + col] =
            __floats2half2_rn(Oa[dt][0] * li0, Oa[dt][1] * li0);
        *(__half2*)&Og[((size_t)(b * SS + s1)) * DIMV + col] =
            __floats2half2_rn(Oa[dt][2] * li1, Oa[dt][3] * li1);
    }
}

// ---------------------------------------------------------------------------
extern "C" void kernel_launch(void* const* d_in, const int* in_sizes, int n_in,
                              void* d_out, int out_size)
{
    (void)in_sizes; (void)n_in; (void)out_size;
    const float* x     = (const float*)d_in[0];
    const float* W_qkv = (const float*)d_in[1];
    const float* b_qkv = (const float*)d_in[2];
    const float* W_out = (const float*)d_in[3];
    const float* b_out = (const float*)d_in[4];
    float* out = (float*)d_out;

    __half *wqt, *wot, *qb, *kb, *vtb, *ath;
    cudaGetSymbolAddress((void**)&wqt, g_wqt);
    cudaGetSymbolAddress((void**)&wot, g_wot);
    cudaGetSymbolAddress((void**)&qb,  g_q);
    cudaGetSymbolAddress((void**)&kb,  g_k);
    cudaGetSymbolAddress((void**)&vtb, g_vt);
    cudaGetSymbolAddress((void**)&ath, g_atth);

    static bool attr_set = false;
    if (!attr_set) {
        cudaFuncSetAttribute(gemm_qkv, cudaFuncAttributeMaxDynamicSharedMemorySize, GEMM_SMEM);
        cudaFuncSetAttribute(gemm_out, cudaFuncAttributeMaxDynamicSharedMemorySize, GEMM_SMEM);
        cudaFuncSetAttribute(flash_f16, cudaFuncAttributeMaxDynamicSharedMemorySize, FLASH_SMEM);
        attr_set = true;
    }

    // 0. stage fp16 transposed weights
    { dim3 g(KDIM / 32, 3 * DIMV / 32); transpose_w<<<g, 256>>>(W_qkv, wqt, 3 * DIMV); }
    { dim3 g(KDIM / 32, DIMV / 32);     transpose_w<<<g, 256>>>(W_out, wot, DIMV); }

    // 1. QKV GEMM (x fp32 converted inline) -> fp16 Q(prescaled)/K + V^T
    { dim3 g(3 * DIMV / 128, MTOT / 128); gemm_qkv<<<g, 256, GEMM_SMEM>>>(x, wqt, b_qkv); }
    // 2. Flash attention -> fp16 [b,s,dim]
    { dim3 g(SS / 128, NH, BB); flash_f16<<<g, 256, FLASH_SMEM>>>(qb, kb, vtb, ath); }
    // 3. Output projection -> fp32 out
    { dim3 g(DIMV / 128, MTOT / 128); gemm_out<<<g, 256, GEMM_SMEM>>>(ath, wot, b_out, out, DIMV); }
}

// round 16
// speedup vs baseline: 1.6906x; 1.1155x over previous
#include <cuda_runtime.h>
#include <cuda_fp16.h>
#include <math.h>

#define DIMV 1024
#define NH 16
#define HD 64
#define BB 2
#define SS 2048
#define MTOT (BB*SS)
#define KDIM 1024

// Scratch buffers.
__device__ __half g_xh  [MTOT*KDIM];        // x fp16 [M][K]
__device__ __half g_wqt [3*DIMV*KDIM];      // W_qkv^T fp16 [N=3072][K]
__device__ __half g_wot [DIMV*KDIM];        // W_out^T fp16 [N=1024][K]
__device__ __half g_q   [BB*NH*SS*HD];      // [b,h,s,d] (pre-scaled)
__device__ __half g_k   [BB*NH*SS*HD];      // [b,h,s,d]
__device__ __half g_vt  [BB*NH*HD*SS];      // [b,h,d,s]
__device__ __half g_atth[MTOT*DIMV];        // attention out fp16
__device__ unsigned g_cnt[128];             // dependency counters (memset 0 per call)

// counter indices
#define C_X   0          // convert_x done      (target 64)
#define C_WQ  1          // wqt transpose done  (target 96)
#define C_WO  2          // wot transpose done  (target 32)
#define C_QKV(nt, b) (3 + (nt) * 2 + (b))    // target 16 each (nt 0..23, b 0..1)
#define C_F(mo)      (51 + (mo))             // flash per (b,qt)=mo, target 16

#define QSCALE (0.125f * 1.44269504088896f)

// ---------------------------------------------------------------------------
// helpers
// ---------------------------------------------------------------------------
__device__ __forceinline__ float ex2f(float x) {
    float y; asm("ex2.approx.f32 %0, %1;" : "=f"(y) : "f"(x)); return y;
}
__device__ __forceinline__ unsigned pack2(float a, float b) {
    __half2 h = __floats2half2_rn(a, b); return *(unsigned*)&h;
}
__device__ __forceinline__ unsigned cvt_h2(float a, float b) {
    unsigned r;
    asm("cvt.rn.f16x2.f32 %0, %1, %2;" : "=r"(r) : "f"(b), "f"(a));
    return r;
}
__device__ __forceinline__ unsigned ex2_h2(unsigned x) {
    unsigned r;
    asm("ex2.approx.f16x2 %0, %1;" : "=r"(r) : "r"(x));
    return r;
}
__device__ __forceinline__ void mma_f16(float* c, const unsigned* a, const unsigned* b) {
    asm volatile(
        "mma.sync.aligned.m16n8k16.row.col.f32.f16.f16.f32 "
        "{%0,%1,%2,%3}, {%4,%5,%6,%7}, {%8,%9}, {%0,%1,%2,%3};"
        : "+f"(c[0]), "+f"(c[1]), "+f"(c[2]), "+f"(c[3])
        : "r"(a[0]), "r"(a[1]), "r"(a[2]), "r"(a[3]), "r"(b[0]), "r"(b[1]));
}
__device__ __forceinline__ int fsw(int r, int k) {
    return r * 64 + (k & 7) + ((((k >> 3) ^ r) & 7)) * 8;
}
__device__ __forceinline__ unsigned smem_u32(const void* p) {
    unsigned a;
    asm("{ .reg .u64 t; cvta.to.shared.u64 t, %1; cvt.u32.u64 %0, t; }" : "=r"(a) : "l"(p));
    return a;
}
__device__ __forceinline__ void ldsm4(unsigned* r, unsigned addr) {
    asm volatile("ldmatrix.sync.aligned.m8n8.x4.shared.b16 {%0,%1,%2,%3}, [%4];"
                 : "=r"(r[0]), "=r"(r[1]), "=r"(r[2]), "=r"(r[3]) : "r"(addr));
}
__device__ __forceinline__ void ldsmA(unsigned* r, unsigned tbase, int mbase, int kbase, int lane) {
    int row = mbase + (lane & 8) + (lane & 7);
    int col = kbase + (lane >> 4) * 8;
    ldsm4(r, tbase + 2 * fsw(row, col));
}
__device__ __forceinline__ void ldsmB(unsigned* r, unsigned tbase, int nbase, int kbase, int lane) {
    int row = nbase + ((lane & 16) >> 1) + (lane & 7);
    int col = kbase + ((lane >> 3) & 1) * 8;
    ldsm4(r, tbase + 2 * fsw(row, col));
}
__device__ __forceinline__ void cp16(unsigned dst, const void* src) {
    asm volatile("cp.async.cg.shared.global [%0], [%1], 16;" :: "r"(dst), "l"(src) : "memory");
}
__device__ __forceinline__ void cp_commit() {
    asm volatile("cp.async.commit_group;" ::: "memory");
}
template<int N> __device__ __forceinline__ void cp_wait() {
    asm volatile("cp.async.wait_group %0;" :: "n"(N) : "memory");
}

// ---- dependency protocol ----
__device__ __forceinline__ void arrive(int idx) {
    __threadfence();
    __syncthreads();
    if (threadIdx.x == 0) atomicAdd(&g_cnt[idx], 1u);
}
__device__ __forceinline__ void spin1(int idx, unsigned target) {
    if (threadIdx.x == 0)
        while (atomicAdd(&g_cnt[idx], 0u) < target) __nanosleep(128);
    __syncthreads();
    __threadfence();
}
__device__ __forceinline__ void spin3(int i0, int i1, int i2, unsigned target) {
    if (threadIdx.x == 0) {
        while (atomicAdd(&g_cnt[i0], 0u) < target) __nanosleep(128);
        while (atomicAdd(&g_cnt[i1], 0u) < target) __nanosleep(128);
        while (atomicAdd(&g_cnt[i2], 0u) < target) __nanosleep(128);
    }
    __syncthreads();
    __threadfence();
}
__device__ __forceinline__ void spin2(int i0, unsigned t0, int i1, unsigned t1) {
    if (threadIdx.x == 0) {
        while (atomicAdd(&g_cnt[i0], 0u) < t0) __nanosleep(128);
        while (atomicAdd(&g_cnt[i1], 0u) < t1) __nanosleep(128);
    }
    __syncthreads();
    __threadfence();
}

#define GSTAGE 32768
#define MEGA_SMEM (3 * GSTAGE)   // 98304 B

// ---------------------------------------------------------------------------
// GEMM body (R13 gemm_hmma, unchanged): 128x128, BK=64, 3-stage cp.async ring.
// MODE 0: QKV scatter epilogue.  MODE 1: fp32 C + bias.
// ---------------------------------------------------------------------------
template<int MODE>
__device__ void gemm_body(char* sm, int bm_idx, int bn_idx,
                          const __half* __restrict__ A, const __half* __restrict__ Bt,
                          const float* __restrict__ bias, float* __restrict__ C, int N)
{
    const unsigned sbase = smem_u32(sm);
    const int tid  = threadIdx.x;
    const int lane = tid & 31;
    const int w    = tid >> 5;
    const int g    = lane >> 2;
    const int tig  = lane & 3;
    const int moff = 32 * (w & 3);
    const int noff = 64 * (w >> 2);
    const int bm   = bm_idx * 128;
    const int bn   = bn_idx * 128;

    float acc[2][8][4];
#pragma unroll
    for (int mt = 0; mt < 2; mt++)
#pragma unroll
        for (int nt = 0; nt < 8; nt++)
#pragma unroll
            for (int i = 0; i < 4; i++) acc[mt][nt][i] = 0.f;

    const int row = tid >> 3;
    const int k8  = (tid & 7) * 8;
    const int swo = 2 * fsw(row, k8);

    auto cp_chunk = [&](int c, int buf) {
        const unsigned ab = sbase + buf * GSTAGE + swo;
        const unsigned bb = ab + 16384;
        const __half* ap = &A [(size_t)(bm + row) * KDIM + c * 64 + k8];
        const __half* bp = &Bt[(size_t)(bn + row) * KDIM + c * 64 + k8];
#pragma unroll
        for (int r = 0; r < 4; r++) {
            cp16(ab + r * 32 * 128, ap + (size_t)(32 * r) * KDIM);
            cp16(bb + r * 32 * 128, bp + (size_t)(32 * r) * KDIM);
        }
        cp_commit();
    };

    const int NCH = KDIM / 64;   // 16
    cp_chunk(0, 0);
    cp_chunk(1, 1);

    for (int c = 0; c < NCH; c++) {
        if (c < NCH - 1) cp_wait<1>(); else cp_wait<0>();
        __syncthreads();
        if (c + 2 < NCH) cp_chunk(c + 2, (c + 2) % 3);

        const int buf = c % 3;
        const unsigned aB = sbase + buf * GSTAGE;
        const unsigned bB = aB + 16384;
#pragma unroll
        for (int ks = 0; ks < 4; ks++) {
            unsigned af[2][4], bf[8][2];
#pragma unroll
            for (int mt = 0; mt < 2; mt++)
                ldsmA(af[mt], aB, moff + 16 * mt, 16 * ks, lane);
#pragma unroll
            for (int ntp = 0; ntp < 4; ntp++) {
                unsigned t4[4];
                ldsmB(t4, bB, noff + 16 * ntp, 16 * ks, lane);
                bf[2 * ntp][0]     = t4[0]; bf[2 * ntp][1]     = t4[1];
                bf[2 * ntp + 1][0] = t4[2]; bf[2 * ntp + 1][1] = t4[3];
            }
#pragma unroll
            for (int mt = 0; mt < 2; mt++)
#pragma unroll
                for (int nt = 0; nt < 8; nt++)
                    mma_f16(acc[mt][nt], af[mt], bf[nt]);
        }
    }

#pragma unroll
    for (int mt = 0; mt < 2; mt++) {
#pragma unroll
        for (int nt = 0; nt < 8; nt++) {
            const int n = bn + noff + 8 * nt + 2 * tig;
            const float bz0 = bias[n], bz1 = bias[n + 1];
#pragma unroll
            for (int half_i = 0; half_i < 2; half_i++) {
                const int m = bm + moff + 16 * mt + g + half_i * 8;
                float v0 = acc[mt][nt][half_i * 2 + 0] + bz0;
                float v1 = acc[mt][nt][half_i * 2 + 1] + bz1;
                if (MODE == 0) {
                    const int which = n >> 10;
                    const int hw = n & 1023;
                    const int hh = hw >> 6;
                    const int dd = hw & 63;
                    const int bI = m >> 11;
                    const int sI = m & 2047;
                    if (which == 2) {
                        const size_t base = ((size_t)(bI * NH + hh) * HD + dd) * SS + sI;
                        g_vt[base]      = __float2half_rn(v0);
                        g_vt[base + SS] = __float2half_rn(v1);
                    } else if (which == 0) {
                        *(__half2*)&g_q[((size_t)(bI * NH + hh) * SS + sI) * HD + dd] =
                            __floats2half2_rn(v0 * QSCALE, v1 * QSCALE);
                    } else {
                        *(__half2*)&g_k[((size_t)(bI * NH + hh) * SS + sI) * HD + dd] =
                            __floats2half2_rn(v0, v1);
                    }
                } else {
                    *(float2*)&C[(size_t)m * N + n] = make_float2(v0, v1);
                }
            }
        }
    }
}

// ---------------------------------------------------------------------------
// Flash body (R13 flash_f16, unchanged).
// ---------------------------------------------------------------------------
#define FQ 0
#define FK(s) (16384 + (s) * 16384)
#define FV(s) (16384 + (s) * 16384 + 8192)

__device__ void flash_body(char* sm, int qt, int h, int b)
{
    const unsigned sbase = smem_u32(sm);
    const int tid  = threadIdx.x;
    const int lane = tid & 31;
    const int w    = tid >> 5;
    const int g    = lane >> 2;
    const int tig  = lane & 3;

    const __half* Qp  = g_q  + ((size_t)(b * NH + h) * SS + qt * 128) * HD;
    const __half* Kp  = g_k  + (size_t)(b * NH + h) * SS * HD;
    const __half* Vtp = g_vt + (size_t)(b * NH + h) * HD * SS;

    const int krow = tid >> 2;
    const int kk8  = (tid & 3) * 16;
    auto cp_tile = [&](int kt, int s) {
        const unsigned kb = sbase + FK(s) + 2 * fsw(krow, kk8);
        const unsigned vb = sbase + FV(s) + 2 * fsw(krow, kk8);
        const __half* kp = &Kp [(size_t)(kt * 64 + krow) * HD + kk8];
        const __half* vp = &Vtp[(size_t)krow * SS + kt * 64 + kk8];
        cp16(kb, kp);                       cp16(vb, vp);
        cp16(kb + 2 * (fsw(krow, kk8 + 8) - fsw(krow, kk8)), kp + 8);
        cp16(vb + 2 * (fsw(krow, kk8 + 8) - fsw(krow, kk8)), vp + 8);
        cp_commit();
    };

#pragma unroll
    for (int r = 0; r < 4; r++) {
        int idx = tid + r * 256;
        int rw  = idx >> 3;
        int k8  = (idx & 7) * 8;
        uint4 v = *(const uint4*)&Qp[rw * HD + k8];
        *(uint4*)(sm + FQ + 2 * fsw(rw, k8)) = v;
    }

    cp_tile(0, 0);
    cp_tile(1, 1);
    __syncthreads();

    unsigned qf[4][4];
#pragma unroll
    for (int dc = 0; dc < 4; dc++)
        ldsmA(qf[dc], sbase + FQ, 16 * w, 16 * dc, lane);

    float m0 = -1e30f, m1 = -1e30f, l0 = 0.f, l1 = 0.f;
    float Oa[8][4];
#pragma unroll
    for (int dt = 0; dt < 8; dt++)
#pragma unroll
        for (int i = 0; i < 4; i++) Oa[dt][i] = 0.f;

    const unsigned ONES2[2] = { 0x3C003C00u, 0x3C003C00u };

    const int NT = SS / 64;
    for (int kt = 0; kt < NT; kt++) {
        if (kt < NT - 1) cp_wait<1>(); else cp_wait<0>();
        __syncthreads();
        if (kt + 2 < NT) cp_tile(kt + 2, (kt + 2) % 3);

        const int buf = kt % 3;
        const unsigned kB = sbase + FK(buf);
        const unsigned vB = sbase + FV(buf);

        float S[8][4];
#pragma unroll
        for (int nt = 0; nt < 8; nt++)
#pragma unroll
            for (int i = 0; i < 4; i++) S[nt][i] = 0.f;
#pragma unroll
        for (int dc = 0; dc < 4; dc++) {
#pragma unroll
            for (int ntp = 0; ntp < 4; ntp++) {
                unsigned t4[4];
                ldsmB(t4, kB, 16 * ntp, 16 * dc, lane);
                mma_f16(S[2 * ntp],     qf[dc], t4);
                mma_f16(S[2 * ntp + 1], qf[dc], t4 + 2);
            }
        }

        float mx0 = S[0][0], mx1 = S[0][2];
#pragma unroll
        for (int nt = 0; nt < 8; nt++) {
            mx0 = fmaxf(mx0, fmaxf(S[nt][0], S[nt][1]));
            mx1 = fmaxf(mx1, fmaxf(S[nt][2], S[nt][3]));
        }
        mx0 = fmaxf(mx0, __shfl_xor_sync(0xffffffffu, mx0, 1));
        mx0 = fmaxf(mx0, __shfl_xor_sync(0xffffffffu, mx0, 2));
        mx1 = fmaxf(mx1, __shfl_xor_sync(0xffffffffu, mx1, 1));
        mx1 = fmaxf(mx1, __shfl_xor_sync(0xffffffffu, mx1, 2));

        const float mn0 = fmaxf(m0, mx0);
        const float mn1 = fmaxf(m1, mx1);
        const float al0 = ex2f(m0 - mn0);
        const float al1 = ex2f(m1 - mn1);
        m0 = mn0; m1 = mn1;

        unsigned P[8][2];
#pragma unroll
        for (int nt = 0; nt < 8; nt++) {
            P[nt][0] = ex2_h2(cvt_h2(S[nt][0] - mn0, S[nt][1] - mn0));
            P[nt][1] = ex2_h2(cvt_h2(S[nt][2] - mn1, S[nt][3] - mn1));
        }

#pragma unroll
        for (int dt = 0; dt < 8; dt++) {
            Oa[dt][0] *= al0; Oa[dt][1] *= al0;
            Oa[dt][2] *= al1; Oa[dt][3] *= al1;
        }

        float lacc[4] = {0.f, 0.f, 0.f, 0.f};
#pragma unroll
        for (int kc = 0; kc < 4; kc++) {
            unsigned pf[4];
            pf[0] = P[2 * kc][0];
            pf[1] = P[2 * kc][1];
            pf[2] = P[2 * kc + 1][0];
            pf[3] = P[2 * kc + 1][1];
            mma_f16(lacc, pf, ONES2);
#pragma unroll
            for (int dtp = 0; dtp < 4; dtp++) {
                unsigned t4[4];
                ldsmB(t4, vB, 16 * dtp, 16 * kc, lane);
                mma_f16(Oa[2 * dtp],     pf, t4);
                mma_f16(Oa[2 * dtp + 1], pf, t4 + 2);
            }
        }
        l0 = l0 * al0 + lacc[0];
        l1 = l1 * al1 + lacc[2];
    }

    const float li0 = 1.f / l0;
    const float li1 = 1.f / l1;
    const int s0 = qt * 128 + 16 * w + g;
    const int s1 = s0 + 8;
#pragma unroll
    for (int dt = 0; dt < 8; dt++) {
        const int col = h * HD + 8 * dt + 2 * tig;
        *(__half2*)&g_atth[((size_t)(b * SS + s0)) * DIMV + col] =
            __floats2half2_rn(Oa[dt][0] * li0, Oa[dt][1] * li0);
        *(__half2*)&g_atth[((size_t)(b * SS + s1)) * DIMV + col] =
            __floats2half2_rn(Oa[dt][2] * li1, Oa[dt][3] * li1);
    }
}

// ---------------------------------------------------------------------------
// Mega kernel: role by blockIdx.
// [0,64): convert_x  [64,160): wqt transpose  [160,192): wot transpose
// [192,960): QKV GEMM  [960,1472): flash  [1472,1728): out-proj GEMM
// ---------------------------------------------------------------------------
__global__ __launch_bounds__(256, 2)
void mega(const float* __restrict__ x,
          const float* __restrict__ W_qkv, const float* __restrict__ b_qkv,
          const float* __restrict__ W_out, const float* __restrict__ b_out,
          float* __restrict__ out)
{
    extern __shared__ char sm[];
    const int bid = blockIdx.x;
    const int tid = threadIdx.x;

    if (bid < 64) {
        // ---- convert x -> fp16 (1,048,576 float4s over 16384 threads) ----
        int idx = bid * 256 + tid;
#pragma unroll 4
        for (int j = 0; j < 64; j++) {
            float4 v = ((const float4*)x)[idx];
            ((uint2*)g_xh)[idx] = make_uint2(pack2(v.x, v.y), pack2(v.z, v.w));
            idx += 16384;
        }
        arrive(C_X);
    } else if (bid < 192) {
        // ---- weight transpose fp32 [K][N] -> fp16 [N][K], 32 tiles per CTA ----
        const bool is_wq = bid < 160;
        const int local = is_wq ? (bid - 64) : (bid - 160);
        const int N = is_wq ? 3 * DIMV : DIMV;
        const float* W = is_wq ? W_qkv : W_out;
        __half* Wt = is_wq ? g_wqt : g_wot;
        float (*t)[33] = (float(*)[33])sm;
        for (int i = 0; i < 32; i++) {
            const int tl = local * 32 + i;
            const int k0 = (tl & 31) * 32;
            const int n0 = (tl >> 5) * 32;
#pragma unroll
            for (int r = 0; r < 4; r++) {
                int k = (tid >> 5) + r * 8;
                int n = tid & 31;
                t[k][n] = W[(size_t)(k0 + k) * N + n0 + n];
            }
            __syncthreads();
#pragma unroll
            for (int r = 0; r < 2; r++) {
                int n  = (tid >> 4) + r * 16;
                int kh = tid & 15;
                *(__half2*)&Wt[(size_t)(n0 + n) * KDIM + k0 + 2 * kh] =
                    __floats2half2_rn(t[2 * kh][n], t[2 * kh + 1][n]);
            }
            __syncthreads();
        }
        arrive(is_wq ? C_WQ : C_WO);
    } else if (bid < 960) {
        // ---- QKV GEMM ----
        const int local = bid - 192;
        const int bm_idx = local / 24;     // m-major: batch 0 tiles first
        const int bn_idx = local % 24;
        spin2(C_X, 64, C_WQ, 96);
        gemm_body<0>(sm, bm_idx, bn_idx, g_xh, g_wqt, b_qkv, nullptr, 3 * DIMV);
        arrive(C_QKV(bn_idx, bm_idx >= 16 ? 1 : 0));
    } else if (bid < 1472) {
        // ---- flash attention ----
        const int local = bid - 960;
        const int qt = local % 16;
        const int h  = (local / 16) % 16;
        const int b  = local / 256;
        spin3(C_QKV(h / 2, b), C_QKV(8 + h / 2, b), C_QKV(16 + h / 2, b), 16);
        flash_body(sm, qt, h, b);
        arrive(C_F(b * 16 + qt));
    } else {
        // ---- output projection ----
        const int local = bid - 1472;
        const int bn_idx = local % 8;
        const int mo     = local / 8;      // = b*16 + qt of the rows it consumes
        spin2(C_F(mo), 16, C_WO, 32);
        gemm_body<1>(sm, mo, bn_idx, g_atth, g_wot, b_out, out, DIMV);
    }
}

// ---------------------------------------------------------------------------
extern "C" void kernel_launch(void* const* d_in, const int* in_sizes, int n_in,
                              void* d_out, int out_size)
{
    (void)in_sizes; (void)n_in; (void)out_size;
    const float* x     = (const float*)d_in[0];
    const float* W_qkv = (const float*)d_in[1];
    const float* b_qkv = (const float*)d_in[2];
    const float* W_out = (const float*)d_in[3];
    const float* b_out = (const float*)d_in[4];
    float* out = (float*)d_out;

    void* cnt_ptr;
    cudaGetSymbolAddress(&cnt_ptr, g_cnt);

    static bool attr_set = false;
    if (!attr_set) {
        cudaFuncSetAttribute(mega, cudaFuncAttributeMaxDynamicSharedMemorySize, MEGA_SMEM);
        attr_set = true;
    }

    cudaMemsetAsync(cnt_ptr, 0, 128 * sizeof(unsigned));
    mega<<<1728, 256, MEGA_SMEM>>>(x, W_qkv, b_qkv, W_out, b_out, out);
}